// round 7
// baseline (speedup 1.0000x reference)
#include <cuda_runtime.h>
#include <cuda_bf16.h>
#include <cstdint>
#include <math.h>

// ---------------- problem constants ----------------
#define BATCH 2
#define SEQ   2048
#define DIM   2048
#define NH    16
#define NKV   8
#define HD    128
#define HALF_HD 64
#define M_ROWS (BATCH * SEQ)          // 4096

// 8-block permutation of the contraction dim: pos = (c&3)*2 | (c>>2)
// => positions (2q, 2q+1) hold original cols (q, q+4)  -> LDS.64 fragment loads
#define PERM8(c) ((((c) & 3) << 1) | ((c) >> 2))

// ---------------- scratch (static device globals; no allocation) ----------------
__device__ float g_xr[(size_t)M_ROWS * DIM];                   // x rounded, K-permuted
__device__ float g_wqkv[(size_t)(2 * DIM) * DIM];              // [wq;wk;wv] rounded, K-permuted (4096x2048)
__device__ float g_wor[(size_t)DIM * DIM];                     // wo rounded, K-permuted
__device__ float g_qkvlin[(size_t)M_ROWS * 2 * DIM];           // x @ wqkv^T  [4096, 4096] fp32
__device__ float g_Q[(size_t)BATCH * NH  * SEQ * HD];          // roped+scaled+rounded, d-permuted
__device__ float g_K[(size_t)BATCH * NKV * SEQ * HD];          // roped+rounded, d-permuted
__device__ float g_Vt[(size_t)BATCH * NKV * HD * SEQ];         // [B,KV,D,S] rounded, s-permuted
__device__ float g_at[(size_t)M_ROWS * DIM];                   // attn out rounded, col-permuted
__device__ float g_cosT[SEQ * HALF_HD];
__device__ float g_sinT[SEQ * HALF_HD];

// ---------------- PTX helpers ----------------
__device__ __forceinline__ uint32_t smem_u32(const void* p) {
    uint32_t a;
    asm("{ .reg .u64 t; cvta.to.shared.u64 t, %1; cvt.u32.u64 %0, t; }" : "=r"(a) : "l"(p));
    return a;
}
__device__ __forceinline__ float f2tf32f(float x) {
    uint32_t r;
    asm("cvt.rna.tf32.f32 %0, %1;" : "=r"(r) : "f"(x));
    return __uint_as_float(r);
}
__device__ __forceinline__ void cp_async16(uint32_t saddr, const void* g) {
    asm volatile("cp.async.cg.shared.global [%0], [%1], 16;" :: "r"(saddr), "l"(g));
}
#define CP_COMMIT() asm volatile("cp.async.commit_group;" ::: "memory")
#define CP_WAIT1()  asm volatile("cp.async.wait_group 1;" ::: "memory")

__device__ __forceinline__ void mma8(float* c, float a0, float a1, float a2, float a3,
                                     float b0, float b1) {
    asm volatile("mma.sync.aligned.m16n8k8.row.col.f32.tf32.tf32.f32 "
        "{%0,%1,%2,%3}, {%4,%5,%6,%7}, {%8,%9}, {%0,%1,%2,%3};"
        : "+f"(c[0]), "+f"(c[1]), "+f"(c[2]), "+f"(c[3])
        : "r"(__float_as_uint(a0)), "r"(__float_as_uint(a1)),
          "r"(__float_as_uint(a2)), "r"(__float_as_uint(a3)),
          "r"(__float_as_uint(b0)), "r"(__float_as_uint(b1)));
}

// ---------------- round + permute copy (tf32-rna, 8-block col perm) ----------------
__global__ void round_perm_kernel(const float* __restrict__ in, float* __restrict__ out, long n) {
    long i = (long)blockIdx.x * blockDim.x + threadIdx.x;
    if (i < n) out[(i & ~7L) | PERM8((int)(i & 7))] = f2tf32f(in[i]);
}

// ---------------- tf32 mma.sync GEMM (inputs pre-rounded + K-permuted) ----------------
// C[M,N] = A[M,K] @ B[N,K]^T
#define AROWA 24
#define AROWB 20

__global__ __launch_bounds__(256) void mma_gemm(
    const float* __restrict__ A, int lda,
    const float* __restrict__ B, int ldb,
    float* __restrict__ C, int ldc, int K)
{
    int m0 = blockIdx.y * 128;
    int n0 = blockIdx.x * 128;
    int nch = K / 16;

    __shared__ float sA[2][128][AROWA];
    __shared__ float sB[2][128][AROWB];

    int tid = threadIdx.x;
    int wid = tid >> 5;
    int lane = tid & 31;
    int wm0 = (wid & 1) * 64;
    int wn0 = (wid >> 1) * 32;
    int grp = lane >> 2;
    int qid = lane & 3;

    const float* Ab = A + (long)m0 * lda;
    const float* Bb = B + (long)n0 * ldb;

    auto issue = [&](int c, int s) {
        int k0 = c * 16;
#pragma unroll
        for (int i = 0; i < 2; i++) {
            int idx = tid + 256 * i;             // 0..511
            int row = idx >> 2;                  // 0..127
            int cc = idx & 3;
            cp_async16(smem_u32(&sA[s][row][cc * 4]), Ab + (long)row * lda + k0 + cc * 4);
            cp_async16(smem_u32(&sB[s][row][cc * 4]), Bb + (long)row * ldb + k0 + cc * 4);
        }
        CP_COMMIT();
    };

    float acc[4][4][4] = {};

    issue(0, 0);
    issue(1, 1);

    for (int c = 0; c < nch; c++) {
        int s = c & 1;
        CP_WAIT1();
        __syncthreads();

#pragma unroll
        for (int ks = 0; ks < 16; ks += 8) {
            float a[4][4];
#pragma unroll
            for (int mi = 0; mi < 4; mi++) {
                int r = wm0 + mi * 16 + grp;
                float2 x0 = *(const float2*)&sA[s][r][ks + qid * 2];
                float2 x1 = *(const float2*)&sA[s][r + 8][ks + qid * 2];
                a[mi][0] = x0.x; a[mi][1] = x1.x; a[mi][2] = x0.y; a[mi][3] = x1.y;
            }
            float b[4][2];
#pragma unroll
            for (int ni = 0; ni < 4; ni++) {
                float2 y = *(const float2*)&sB[s][wn0 + ni * 8 + grp][ks + qid * 2];
                b[ni][0] = y.x; b[ni][1] = y.y;
            }
#pragma unroll
            for (int mi = 0; mi < 4; mi++)
#pragma unroll
                for (int ni = 0; ni < 4; ni++)
                    mma8(acc[mi][ni], a[mi][0], a[mi][1], a[mi][2], a[mi][3], b[ni][0], b[ni][1]);
        }
        __syncthreads();
        if (c + 2 < nch) issue(c + 2, s);
    }

#pragma unroll
    for (int mi = 0; mi < 4; mi++) {
#pragma unroll
        for (int ni = 0; ni < 4; ni++) {
            int row = m0 + wm0 + mi * 16 + grp;
            int col = n0 + wn0 + ni * 8 + 2 * qid;
            *(float2*)(C + (long)row * ldc + col) = make_float2(acc[mi][ni][0], acc[mi][ni][1]);
            *(float2*)(C + (long)(row + 8) * ldc + col) = make_float2(acc[mi][ni][2], acc[mi][ni][3]);
        }
    }
}

// ---------------- flash attention v2: 2-stage cp.async pipeline, Bk=32 ----------------
// Bq=128, Bk=32, 8 warps x 16 rows. Q pre-scaled; Q/K d-permuted; Vt key-permuted.
#define SQ_F   (128 * 136)            // 17408 floats
#define SK_F   (32 * 136)             // 4352
#define SV_F   (128 * 40)             // 5120 (32 keys + 8 pad per d-row)
#define SSTAGE (SK_F + SV_F)          // 9472
#define SP_F   (8 * 16 * 40)          // 5120 (per-warp 16x40)
#define FLASH_SMEM ((SQ_F + 2 * SSTAGE + SP_F) * 4)   // 165888 B

__global__ __launch_bounds__(256) void flash_kernel(
    const float* __restrict__ Q, const float* __restrict__ K,
    const float* __restrict__ Vt, float* __restrict__ at)
{
    extern __shared__ float sm[];
    float* sQ = sm;

    int tid = threadIdx.x, wid = tid >> 5, lane = tid & 31;
    int grp = lane >> 2, qid = lane & 3;
    float* sP = sm + SQ_F + 2 * SSTAGE + wid * (16 * 40);

    int bh = blockIdx.y;
    int b = bh >> 4, h = bh & 15, kv = h >> 1;
    int qt = (int)gridDim.x - 1 - (int)blockIdx.x;     // big tiles first
    int qbase = qt * 128;
    const float* Qg = Q + (size_t)(b * NH + h) * SEQ * HD;
    const float* Kg = K + (size_t)(b * NKV + kv) * SEQ * HD;
    const float* Vg = Vt + (size_t)(b * NKV + kv) * HD * SEQ;

    int nkt = 4 * qt + 4;                              // 32-key tiles to cover qbase+128 keys

    // cp.async issue of K/V stage: K 32x128 (1024 f4), V 128x32 (1024 f4) -> 8 f4/thread
    auto issue = [&](int kt, int s) {
        float* sK = sm + SQ_F + s * SSTAGE;
        float* sV = sK + SK_F;
#pragma unroll
        for (int i = 0; i < 4; i++) {
            int idx = tid + 256 * i;                   // 0..1023
            int krow = idx >> 5, kc4 = idx & 31;       // K: 32 rows x 32 chunks
            cp_async16(smem_u32(sK + krow * 136 + kc4 * 4),
                       Kg + (size_t)(kt * 32 + krow) * HD + kc4 * 4);
            int vrow = idx >> 3, vc4 = idx & 7;        // V: 128 rows x 8 chunks
            cp_async16(smem_u32(sV + vrow * 40 + vc4 * 4),
                       Vg + (size_t)vrow * SEQ + kt * 32 + vc4 * 4);
        }
        CP_COMMIT();
    };

    issue(0, 0);
    issue(1, 1);

    // load Q tile (overlaps the in-flight cp.async stages)
#pragma unroll
    for (int i = 0; i < 16; i++) {
        int idx = tid + 256 * i;                       // 128 rows x 32 float4
        int row = idx >> 5, c4 = idx & 31;
        float4 v = *(const float4*)(Qg + (size_t)(qbase + row) * HD + c4 * 4);
        *(float4*)(sQ + row * 136 + c4 * 4) = v;
    }

    float o[16][4];
#pragma unroll
    for (int i = 0; i < 16; i++) { o[i][0] = o[i][1] = o[i][2] = o[i][3] = 0.f; }
    float m0 = -1e30f, m1 = -1e30f, l0 = 0.f, l1 = 0.f;

    int r0 = qbase + wid * 16 + grp;                   // lane rows r0, r0+8
    int pp0 = PERM8(2 * qid), pp1 = PERM8(2 * qid + 1);

    for (int kt = 0; kt < nkt; kt++) {
        int s = kt & 1;
        float* sK = sm + SQ_F + s * SSTAGE;
        float* sV = sK + SK_F;
        CP_WAIT1();
        __syncthreads();

        if (kt * 32 <= qbase + wid * 16 + 15) {        // warp has unmasked rows this tile
            // ---- S = Q @ K^T (scale pre-folded into Q) ----
            float sc[4][4];
#pragma unroll
            for (int ni = 0; ni < 4; ni++) { sc[ni][0] = sc[ni][1] = sc[ni][2] = sc[ni][3] = 0.f; }
            const float* q0 = sQ + (wid * 16 + grp) * 136 + qid * 2;
            const float* q1 = q0 + 8 * 136;
#pragma unroll
            for (int kk = 0; kk < 16; kk++) {
                float2 a02 = *(const float2*)(q0 + kk * 8);
                float2 a13 = *(const float2*)(q1 + kk * 8);
#pragma unroll
                for (int ni = 0; ni < 4; ni++) {
                    float2 b01 = *(const float2*)(sK + (ni * 8 + grp) * 136 + kk * 8 + qid * 2);
                    mma8(sc[ni], a02.x, a13.x, a02.y, a13.y, b01.x, b01.y);
                }
            }

            // ---- causal mask ----
            if (kt * 32 + 31 > qbase + wid * 16) {
#pragma unroll
                for (int ni = 0; ni < 4; ni++) {
                    int c0 = kt * 32 + ni * 8 + 2 * qid;
                    if (c0 > r0)         sc[ni][0] = -1e30f;
                    if (c0 + 1 > r0)     sc[ni][1] = -1e30f;
                    if (c0 > r0 + 8)     sc[ni][2] = -1e30f;
                    if (c0 + 1 > r0 + 8) sc[ni][3] = -1e30f;
                }
            }

            // ---- online softmax (rows r0, r0+8; quad-lane reductions) ----
            float mx0 = -1e30f, mx1 = -1e30f;
#pragma unroll
            for (int ni = 0; ni < 4; ni++) {
                mx0 = fmaxf(mx0, fmaxf(sc[ni][0], sc[ni][1]));
                mx1 = fmaxf(mx1, fmaxf(sc[ni][2], sc[ni][3]));
            }
            mx0 = fmaxf(mx0, __shfl_xor_sync(0xffffffffu, mx0, 1));
            mx0 = fmaxf(mx0, __shfl_xor_sync(0xffffffffu, mx0, 2));
            mx1 = fmaxf(mx1, __shfl_xor_sync(0xffffffffu, mx1, 1));
            mx1 = fmaxf(mx1, __shfl_xor_sync(0xffffffffu, mx1, 2));
            float mn0 = fmaxf(m0, mx0), mn1 = fmaxf(m1, mx1);
            float al0 = __expf(m0 - mn0), al1 = __expf(m1 - mn1);
            m0 = mn0; m1 = mn1;
            float sum0 = 0.f, sum1 = 0.f;
#pragma unroll
            for (int ni = 0; ni < 4; ni++) {
                sc[ni][0] = __expf(sc[ni][0] - mn0); sum0 += sc[ni][0];
                sc[ni][1] = __expf(sc[ni][1] - mn0); sum0 += sc[ni][1];
                sc[ni][2] = __expf(sc[ni][2] - mn1); sum1 += sc[ni][2];
                sc[ni][3] = __expf(sc[ni][3] - mn1); sum1 += sc[ni][3];
            }
            sum0 += __shfl_xor_sync(0xffffffffu, sum0, 1);
            sum0 += __shfl_xor_sync(0xffffffffu, sum0, 2);
            sum1 += __shfl_xor_sync(0xffffffffu, sum1, 1);
            sum1 += __shfl_xor_sync(0xffffffffu, sum1, 2);
            l0 = l0 * al0 + sum0;
            l1 = l1 * al1 + sum1;
#pragma unroll
            for (int ni = 0; ni < 16; ni++) {
                o[ni][0] *= al0; o[ni][1] *= al0;
                o[ni][2] *= al1; o[ni][3] *= al1;
            }

            // ---- stage P (rounded, key-permuted) into warp-private SMEM ----
#pragma unroll
            for (int ni = 0; ni < 4; ni++) {
                sP[grp * 40 + ni * 8 + pp0]       = f2tf32f(sc[ni][0]);
                sP[grp * 40 + ni * 8 + pp1]       = f2tf32f(sc[ni][1]);
                sP[(grp + 8) * 40 + ni * 8 + pp0] = f2tf32f(sc[ni][2]);
                sP[(grp + 8) * 40 + ni * 8 + pp1] = f2tf32f(sc[ni][3]);
            }
            __syncwarp();

            // ---- O += P @ V ----
            float2 pa0[4], pa1[4];
#pragma unroll
            for (int kk = 0; kk < 4; kk++) {
                pa0[kk] = *(const float2*)(sP + grp * 40 + kk * 8 + qid * 2);
                pa1[kk] = *(const float2*)(sP + (grp + 8) * 40 + kk * 8 + qid * 2);
            }
#pragma unroll
            for (int ni = 0; ni < 16; ni++) {
#pragma unroll
                for (int kk = 0; kk < 4; kk++) {
                    float2 b01 = *(const float2*)(sV + (ni * 8 + grp) * 40 + kk * 8 + qid * 2);
                    mma8(o[ni], pa0[kk].x, pa1[kk].x, pa0[kk].y, pa1[kk].y, b01.x, b01.y);
                }
            }
            __syncwarp();
        }

        __syncthreads();
        if (kt + 2 < nkt) issue(kt + 2, s);
    }

    // ---- epilogue: normalize, round, store (col-permuted for out proj) ----
    float inv0 = 1.f / l0, inv1 = 1.f / l1;
    float* a0p = at + (size_t)(b * SEQ + r0) * DIM + h * HD;
    float* a1p = at + (size_t)(b * SEQ + r0 + 8) * DIM + h * HD;
#pragma unroll
    for (int ni = 0; ni < 16; ni++) {
        a0p[ni * 8 + pp0] = f2tf32f(o[ni][0] * inv0);
        a0p[ni * 8 + pp1] = f2tf32f(o[ni][1] * inv0);
        a1p[ni * 8 + pp0] = f2tf32f(o[ni][2] * inv1);
        a1p[ni * 8 + pp1] = f2tf32f(o[ni][3] * inv1);
    }
}

// ---------------- RoPE table (fp32 angle, fp64 sincos) ----------------
__global__ void rope_table_kernel(float* cosT, float* sinT) {
    int s = blockIdx.x;
    int i = threadIdx.x;
    float inv = (float)pow(10000.0, -(double)(2 * i) / (double)HD);
    float ang = (float)s * inv;
    double a = (double)ang;
    cosT[s * HALF_HD + i] = (float)cos(a);
    sinT[s * HALF_HD + i] = (float)sin(a);
}

// ---------------- RoPE apply + transpose (+scale for Q) + round + d-perm ----------------
__global__ void rope_q_kernel(const float* __restrict__ qkvlin, const float* __restrict__ cosT,
                              const float* __restrict__ sinT, float* __restrict__ Q) {
    long idx = (long)blockIdx.x * blockDim.x + threadIdx.x;
    if (idx >= (long)BATCH * SEQ * NH * HALF_HD) return;
    int i = idx & (HALF_HD - 1);
    long t = idx >> 6;
    int h = t & (NH - 1); t >>= 4;
    int s = t & (SEQ - 1);
    int b = (int)(t >> 11);
    const float* src = qkvlin + ((long)(b * SEQ + s)) * (2 * DIM) + h * HD + 2 * i;
    float xr = src[0], xi = src[1];
    float c = cosT[s * HALF_HD + i], sn = sinT[s * HALF_HD + i];
    const float scale = 0.088388347648318447f;   // 1/sqrt(128)
    float* dst = Q + (((long)(b * NH + h) * SEQ + s)) * HD;
    int cr = 2 * i, ci = 2 * i + 1;
    dst[(cr & ~7) | PERM8(cr & 7)] = f2tf32f(scale * (xr * c - xi * sn));
    dst[(ci & ~7) | PERM8(ci & 7)] = f2tf32f(scale * (xr * sn + xi * c));
}

__global__ void rope_k_kernel(const float* __restrict__ qkvlin, const float* __restrict__ cosT,
                              const float* __restrict__ sinT, float* __restrict__ K) {
    long idx = (long)blockIdx.x * blockDim.x + threadIdx.x;
    if (idx >= (long)BATCH * SEQ * NKV * HALF_HD) return;
    int i = idx & (HALF_HD - 1);
    long t = idx >> 6;
    int h = t & (NKV - 1); t >>= 3;
    int s = t & (SEQ - 1);
    int b = (int)(t >> 11);
    const float* src = qkvlin + ((long)(b * SEQ + s)) * (2 * DIM) + DIM + h * HD + 2 * i;
    float xr = src[0], xi = src[1];
    float c = cosT[s * HALF_HD + i], sn = sinT[s * HALF_HD + i];
    float* dst = K + (((long)(b * NKV + h) * SEQ + s)) * HD;
    int cr = 2 * i, ci = 2 * i + 1;
    dst[(cr & ~7) | PERM8(cr & 7)] = f2tf32f(xr * c - xi * sn);
    dst[(ci & ~7) | PERM8(ci & 7)] = f2tf32f(xr * sn + xi * c);
}

// V transpose: qkvlin v-part [b,s,h,d] -> Vt[b,h,d,s'] (rounded, s 8-block permuted)
// V columns live at [DIM + NKV*HD, 2*DIM) of qkvlin.
__global__ void v_transpose_kernel(const float* __restrict__ qkvlin, float* __restrict__ Vt) {
    __shared__ float t[32][33];
    int bh = blockIdx.z;
    int b = bh >> 3, h = bh & 7;
    int s0 = blockIdx.x * 32, d0 = blockIdx.y * 32;
    int tx = threadIdx.x, ty = threadIdx.y;
    for (int i = ty; i < 32; i += 8)
        t[i][tx] = qkvlin[((long)(b * SEQ + s0 + i)) * (2 * DIM) + (DIM + NKV * HD) + h * HD + d0 + tx];
    __syncthreads();
    int sp = (tx & ~7) | PERM8(tx & 7);
    for (int i = ty; i < 32; i += 8)
        Vt[((long)bh * HD + d0 + i) * SEQ + s0 + sp] = f2tf32f(t[tx][i]);
}

// ---------------- launch ----------------
extern "C" void kernel_launch(void* const* d_in, const int* in_sizes, int n_in,
                              void* d_out, int out_size) {
    const float* x  = (const float*)d_in[0];
    const float* wq = (const float*)d_in[1];
    const float* wk = (const float*)d_in[2];
    const float* wv = (const float*)d_in[3];
    const float* wo = (const float*)d_in[4];
    float* out = (float*)d_out;

    float* xr;   cudaGetSymbolAddress((void**)&xr,   g_xr);
    float* wqkv; cudaGetSymbolAddress((void**)&wqkv, g_wqkv);
    float* wor;  cudaGetSymbolAddress((void**)&wor,  g_wor);
    float* qkvl; cudaGetSymbolAddress((void**)&qkvl, g_qkvlin);
    float* Q;    cudaGetSymbolAddress((void**)&Q,    g_Q);
    float* Kd;   cudaGetSymbolAddress((void**)&Kd,   g_K);
    float* Vt;   cudaGetSymbolAddress((void**)&Vt,   g_Vt);
    float* at;   cudaGetSymbolAddress((void**)&at,   g_at);
    float* cT;   cudaGetSymbolAddress((void**)&cT,   g_cosT);
    float* sT;   cudaGetSymbolAddress((void**)&sT,   g_sinT);

    cudaFuncSetAttribute(flash_kernel, cudaFuncAttributeMaxDynamicSharedMemorySize, FLASH_SMEM);

    // 0) round+permute inputs; concat wq/wk/wv
    {
        long nx = (long)M_ROWS * DIM;
        round_perm_kernel<<<(unsigned)((nx + 255) / 256), 256>>>(x, xr, nx);
        long nw = (long)DIM * DIM;               // wq: 2048x2048
        long nk = (long)(NKV * HD) * DIM;        // wk/wv: 1024x2048
        round_perm_kernel<<<(unsigned)((nw + 255) / 256), 256>>>(wq, wqkv, nw);
        round_perm_kernel<<<(unsigned)((nk + 255) / 256), 256>>>(wk, wqkv + (long)DIM * DIM, nk);
        round_perm_kernel<<<(unsigned)((nk + 255) / 256), 256>>>(wv, wqkv + (long)(DIM + NKV * HD) * DIM, nk);
        round_perm_kernel<<<(unsigned)((nw + 255) / 256), 256>>>(wo, wor, nw);
    }

    // 1) RoPE table
    rope_table_kernel<<<SEQ, HALF_HD>>>(cT, sT);

    // 2) fused QKV projection: qkvlin[4096,4096] = xr @ wqkv^T
    mma_gemm<<<dim3(2 * DIM / 128, M_ROWS / 128), 256>>>(
        xr, DIM, wqkv, DIM, qkvl, 2 * DIM, DIM);

    // 3) RoPE + transposes (round + permute outputs)
    {
        long nq = (long)BATCH * SEQ * NH * HALF_HD;
        rope_q_kernel<<<(unsigned)((nq + 255) / 256), 256>>>(qkvl, cT, sT, Q);
        long nk = (long)BATCH * SEQ * NKV * HALF_HD;
        rope_k_kernel<<<(unsigned)((nk + 255) / 256), 256>>>(qkvl, cT, sT, Kd);
        v_transpose_kernel<<<dim3(SEQ / 32, HD / 32, BATCH * NKV), dim3(32, 8)>>>(qkvl, Vt);
    }

    // 4) fused causal attention -> at
    flash_kernel<<<dim3(SEQ / 128, BATCH * NH), 256, FLASH_SMEM>>>(Q, Kd, Vt, at);

    // 5) out = at @ wo^T
    mma_gemm<<<dim3(DIM / 128, M_ROWS / 128), 256>>>(
        at, DIM, wor, DIM, out, DIM, DIM);

    (void)in_sizes; (void)n_in; (void)out_size;
}

// round 8
// speedup vs baseline: 1.0725x; 1.0725x over previous
#include <cuda_runtime.h>
#include <cuda_bf16.h>
#include <cstdint>
#include <math.h>

// ---------------- problem constants ----------------
#define BATCH 2
#define SEQ   2048
#define DIM   2048
#define NH    16
#define NKV   8
#define HD    128
#define HALF_HD 64
#define M_ROWS (BATCH * SEQ)          // 4096

// 8-block permutation of the contraction dim: pos = (c&3)*2 | (c>>2)
// => positions (2q, 2q+1) hold original cols (q, q+4)  -> LDS.64/LDG.64 fragment loads
#define PERM8(c) ((((c) & 3) << 1) | ((c) >> 2))

// ---------------- scratch (static device globals; no allocation) ----------------
__device__ float g_xr[(size_t)M_ROWS * DIM];                   // x rounded, K-permuted
__device__ float g_wqkv[(size_t)(2 * DIM) * DIM];              // [wq;wk;wv] rounded, K-permuted (4096x2048)
__device__ float g_wor[(size_t)DIM * DIM];                     // wo rounded, K-permuted
__device__ float g_qkvlin[(size_t)M_ROWS * 2 * DIM];           // x @ wqkv^T  [4096, 4096] fp32
__device__ float g_Q[(size_t)BATCH * NH  * SEQ * HD];          // roped+scaled+rounded, d-permuted
__device__ float g_K[(size_t)BATCH * NKV * SEQ * HD];          // roped+rounded, d-permuted
__device__ float g_Vt[(size_t)BATCH * NKV * HD * SEQ];         // [B,KV,D,S] rounded, s-permuted
__device__ float g_at[(size_t)M_ROWS * DIM];                   // attn out rounded, col-permuted
__device__ float g_cosT[SEQ * HALF_HD];
__device__ float g_sinT[SEQ * HALF_HD];

// ---------------- PTX helpers ----------------
__device__ __forceinline__ uint32_t smem_u32(const void* p) {
    uint32_t a;
    asm("{ .reg .u64 t; cvta.to.shared.u64 t, %1; cvt.u32.u64 %0, t; }" : "=r"(a) : "l"(p));
    return a;
}
__device__ __forceinline__ float f2tf32f(float x) {
    uint32_t r;
    asm("cvt.rna.tf32.f32 %0, %1;" : "=r"(r) : "f"(x));
    return __uint_as_float(r);
}
__device__ __forceinline__ void cp_async16(uint32_t saddr, const void* g) {
    asm volatile("cp.async.cg.shared.global [%0], [%1], 16;" :: "r"(saddr), "l"(g));
}
#define CP_COMMIT() asm volatile("cp.async.commit_group;" ::: "memory")
#define CP_WAIT1()  asm volatile("cp.async.wait_group 1;" ::: "memory")

__device__ __forceinline__ void mma8(float* c, float a0, float a1, float a2, float a3,
                                     float b0, float b1) {
    asm volatile("mma.sync.aligned.m16n8k8.row.col.f32.tf32.tf32.f32 "
        "{%0,%1,%2,%3}, {%4,%5,%6,%7}, {%8,%9}, {%0,%1,%2,%3};"
        : "+f"(c[0]), "+f"(c[1]), "+f"(c[2]), "+f"(c[3])
        : "r"(__float_as_uint(a0)), "r"(__float_as_uint(a1)),
          "r"(__float_as_uint(a2)), "r"(__float_as_uint(a3)),
          "r"(__float_as_uint(b0)), "r"(__float_as_uint(b1)));
}

// ---------------- round + permute copy (tf32-rna, 8-block col perm) ----------------
__global__ void round_perm_kernel(const float* __restrict__ in, float* __restrict__ out, long n) {
    long i = (long)blockIdx.x * blockDim.x + threadIdx.x;
    if (i < n) out[(i & ~7L) | PERM8((int)(i & 7))] = f2tf32f(in[i]);
}

// ---------------- tf32 mma.sync GEMM (inputs pre-rounded + K-permuted) ----------------
// C[M,N] = A[M,K] @ B[N,K]^T
#define AROWA 24
#define AROWB 20

__global__ __launch_bounds__(256) void mma_gemm(
    const float* __restrict__ A, int lda,
    const float* __restrict__ B, int ldb,
    float* __restrict__ C, int ldc, int K)
{
    int m0 = blockIdx.y * 128;
    int n0 = blockIdx.x * 128;
    int nch = K / 16;

    __shared__ float sA[2][128][AROWA];
    __shared__ float sB[2][128][AROWB];

    int tid = threadIdx.x;
    int wid = tid >> 5;
    int lane = tid & 31;
    int wm0 = (wid & 1) * 64;
    int wn0 = (wid >> 1) * 32;
    int grp = lane >> 2;
    int qid = lane & 3;

    const float* Ab = A + (long)m0 * lda;
    const float* Bb = B + (long)n0 * ldb;

    auto issue = [&](int c, int s) {
        int k0 = c * 16;
#pragma unroll
        for (int i = 0; i < 2; i++) {
            int idx = tid + 256 * i;             // 0..511
            int row = idx >> 2;                  // 0..127
            int cc = idx & 3;
            cp_async16(smem_u32(&sA[s][row][cc * 4]), Ab + (long)row * lda + k0 + cc * 4);
            cp_async16(smem_u32(&sB[s][row][cc * 4]), Bb + (long)row * ldb + k0 + cc * 4);
        }
        CP_COMMIT();
    };

    float acc[4][4][4] = {};

    issue(0, 0);
    issue(1, 1);

    for (int c = 0; c < nch; c++) {
        int s = c & 1;
        CP_WAIT1();
        __syncthreads();

#pragma unroll
        for (int ks = 0; ks < 16; ks += 8) {
            float a[4][4];
#pragma unroll
            for (int mi = 0; mi < 4; mi++) {
                int r = wm0 + mi * 16 + grp;
                float2 x0 = *(const float2*)&sA[s][r][ks + qid * 2];
                float2 x1 = *(const float2*)&sA[s][r + 8][ks + qid * 2];
                a[mi][0] = x0.x; a[mi][1] = x1.x; a[mi][2] = x0.y; a[mi][3] = x1.y;
            }
            float b[4][2];
#pragma unroll
            for (int ni = 0; ni < 4; ni++) {
                float2 y = *(const float2*)&sB[s][wn0 + ni * 8 + grp][ks + qid * 2];
                b[ni][0] = y.x; b[ni][1] = y.y;
            }
#pragma unroll
            for (int mi = 0; mi < 4; mi++)
#pragma unroll
                for (int ni = 0; ni < 4; ni++)
                    mma8(acc[mi][ni], a[mi][0], a[mi][1], a[mi][2], a[mi][3], b[ni][0], b[ni][1]);
        }
        __syncthreads();
        if (c + 2 < nch) issue(c + 2, s);
    }

#pragma unroll
    for (int mi = 0; mi < 4; mi++) {
#pragma unroll
        for (int ni = 0; ni < 4; ni++) {
            int row = m0 + wm0 + mi * 16 + grp;
            int col = n0 + wn0 + ni * 8 + 2 * qid;
            *(float2*)(C + (long)row * ldc + col) = make_float2(acc[mi][ni][0], acc[mi][ni][1]);
            *(float2*)(C + (long)(row + 8) * ldc + col) = make_float2(acc[mi][ni][2], acc[mi][ni][3]);
        }
    }
}

// ---------------- flash attention v3: Bq=64, 4 warps, Q in regs, 2 CTAs/SM ----------------
#define SKF (32 * 136)                 // K stage: 4352 floats
#define SVF (128 * 40)                 // V stage: 5120 floats
#define SST (SKF + SVF)                // 9472
#define SPF (4 * 16 * 40)              // 2560 (per-warp 16x40 P buffers)
#define FLASH_SMEM ((2 * SST + SPF) * 4)   // 86016 B -> 2 CTAs/SM

__global__ __launch_bounds__(128) void flash_kernel(
    const float* __restrict__ Q, const float* __restrict__ K,
    const float* __restrict__ Vt, float* __restrict__ at)
{
    extern __shared__ float sm[];

    int tid = threadIdx.x, wid = tid >> 5, lane = tid & 31;
    int grp = lane >> 2, qid = lane & 3;
    float* sP = sm + 2 * SST + wid * (16 * 40);

    int bh = blockIdx.y;
    int b = bh >> 4, h = bh & 15, kv = h >> 1;
    int qt = (int)gridDim.x - 1 - (int)blockIdx.x;     // big tiles first
    int qbase = qt * 64;
    const float* Qg = Q + (size_t)(b * NH + h) * SEQ * HD;
    const float* Kg = K + (size_t)(b * NKV + kv) * SEQ * HD;
    const float* Vg = Vt + (size_t)(b * NKV + kv) * HD * SEQ;

    int nkt = 2 * qt + 2;                              // 32-key tiles covering qbase+64 keys

    // cp.async stage fill: K 32x128 (1024 f4) + V 128x32 (1024 f4) over 128 threads
    auto issue = [&](int kt, int s) {
        float* sK = sm + s * SST;
        float* sV = sK + SKF;
#pragma unroll
        for (int i = 0; i < 8; i++) {
            int idx = tid + 128 * i;                   // 0..1023
            int krow = idx >> 5, kc4 = idx & 31;       // K: 32 rows x 32 chunks
            cp_async16(smem_u32(sK + krow * 136 + kc4 * 4),
                       Kg + (size_t)(kt * 32 + krow) * HD + kc4 * 4);
            int vrow = idx >> 3, vc4 = idx & 7;        // V: 128 rows x 8 chunks
            cp_async16(smem_u32(sV + vrow * 40 + vc4 * 4),
                       Vg + (size_t)vrow * SEQ + kt * 32 + vc4 * 4);
        }
        CP_COMMIT();
    };

    issue(0, 0);
    issue(1, 1);

    // ---- load this warp's Q rows (r0, r0+8) into registers (overlaps cp.async) ----
    int r0 = qbase + wid * 16 + grp;
    float2 qa[16], qb[16];                             // per k-chunk: cols (2q,2q+1)-permuted
#pragma unroll
    for (int kk = 0; kk < 16; kk++) {
        qa[kk] = *(const float2*)(Qg + (size_t)r0 * HD + kk * 8 + qid * 2);
        qb[kk] = *(const float2*)(Qg + (size_t)(r0 + 8) * HD + kk * 8 + qid * 2);
    }

    float o[16][4];
#pragma unroll
    for (int i = 0; i < 16; i++) { o[i][0] = o[i][1] = o[i][2] = o[i][3] = 0.f; }
    float m0 = -1e30f, m1 = -1e30f, l0 = 0.f, l1 = 0.f;
    int pp0 = PERM8(2 * qid), pp1 = PERM8(2 * qid + 1);

    for (int kt = 0; kt < nkt; kt++) {
        int s = kt & 1;
        float* sK = sm + s * SST;
        float* sV = sK + SKF;
        CP_WAIT1();
        __syncthreads();

        if (kt * 32 <= qbase + wid * 16 + 15) {        // warp has unmasked rows this tile
            // ---- S = Q @ K^T (A from registers; scale pre-folded into Q) ----
            float sc[4][4];
#pragma unroll
            for (int ni = 0; ni < 4; ni++) { sc[ni][0] = sc[ni][1] = sc[ni][2] = sc[ni][3] = 0.f; }
#pragma unroll
            for (int kk = 0; kk < 16; kk++) {
#pragma unroll
                for (int ni = 0; ni < 4; ni++) {
                    float2 b01 = *(const float2*)(sK + (ni * 8 + grp) * 136 + kk * 8 + qid * 2);
                    mma8(sc[ni], qa[kk].x, qb[kk].x, qa[kk].y, qb[kk].y, b01.x, b01.y);
                }
            }

            // ---- causal mask ----
            if (kt * 32 + 31 > qbase + wid * 16) {
#pragma unroll
                for (int ni = 0; ni < 4; ni++) {
                    int c0 = kt * 32 + ni * 8 + 2 * qid;
                    if (c0 > r0)         sc[ni][0] = -1e30f;
                    if (c0 + 1 > r0)     sc[ni][1] = -1e30f;
                    if (c0 > r0 + 8)     sc[ni][2] = -1e30f;
                    if (c0 + 1 > r0 + 8) sc[ni][3] = -1e30f;
                }
            }

            // ---- online softmax (rows r0, r0+8; quad-lane reductions) ----
            float mx0 = -1e30f, mx1 = -1e30f;
#pragma unroll
            for (int ni = 0; ni < 4; ni++) {
                mx0 = fmaxf(mx0, fmaxf(sc[ni][0], sc[ni][1]));
                mx1 = fmaxf(mx1, fmaxf(sc[ni][2], sc[ni][3]));
            }
            mx0 = fmaxf(mx0, __shfl_xor_sync(0xffffffffu, mx0, 1));
            mx0 = fmaxf(mx0, __shfl_xor_sync(0xffffffffu, mx0, 2));
            mx1 = fmaxf(mx1, __shfl_xor_sync(0xffffffffu, mx1, 1));
            mx1 = fmaxf(mx1, __shfl_xor_sync(0xffffffffu, mx1, 2));
            float mn0 = fmaxf(m0, mx0), mn1 = fmaxf(m1, mx1);
            float al0 = __expf(m0 - mn0), al1 = __expf(m1 - mn1);
            m0 = mn0; m1 = mn1;
            float sum0 = 0.f, sum1 = 0.f;
#pragma unroll
            for (int ni = 0; ni < 4; ni++) {
                sc[ni][0] = __expf(sc[ni][0] - mn0); sum0 += sc[ni][0];
                sc[ni][1] = __expf(sc[ni][1] - mn0); sum0 += sc[ni][1];
                sc[ni][2] = __expf(sc[ni][2] - mn1); sum1 += sc[ni][2];
                sc[ni][3] = __expf(sc[ni][3] - mn1); sum1 += sc[ni][3];
            }
            sum0 += __shfl_xor_sync(0xffffffffu, sum0, 1);
            sum0 += __shfl_xor_sync(0xffffffffu, sum0, 2);
            sum1 += __shfl_xor_sync(0xffffffffu, sum1, 1);
            sum1 += __shfl_xor_sync(0xffffffffu, sum1, 2);
            l0 = l0 * al0 + sum0;
            l1 = l1 * al1 + sum1;
#pragma unroll
            for (int ni = 0; ni < 16; ni++) {
                o[ni][0] *= al0; o[ni][1] *= al0;
                o[ni][2] *= al1; o[ni][3] *= al1;
            }

            // ---- stage P (rounded, key-permuted) into warp-private SMEM ----
#pragma unroll
            for (int ni = 0; ni < 4; ni++) {
                sP[grp * 40 + ni * 8 + pp0]       = f2tf32f(sc[ni][0]);
                sP[grp * 40 + ni * 8 + pp1]       = f2tf32f(sc[ni][1]);
                sP[(grp + 8) * 40 + ni * 8 + pp0] = f2tf32f(sc[ni][2]);
                sP[(grp + 8) * 40 + ni * 8 + pp1] = f2tf32f(sc[ni][3]);
            }
            __syncwarp();

            // ---- O += P @ V ----
            float2 pa0[4], pa1[4];
#pragma unroll
            for (int kk = 0; kk < 4; kk++) {
                pa0[kk] = *(const float2*)(sP + grp * 40 + kk * 8 + qid * 2);
                pa1[kk] = *(const float2*)(sP + (grp + 8) * 40 + kk * 8 + qid * 2);
            }
#pragma unroll
            for (int ni = 0; ni < 16; ni++) {
#pragma unroll
                for (int kk = 0; kk < 4; kk++) {
                    float2 b01 = *(const float2*)(sV + (ni * 8 + grp) * 40 + kk * 8 + qid * 2);
                    mma8(o[ni], pa0[kk].x, pa1[kk].x, pa0[kk].y, pa1[kk].y, b01.x, b01.y);
                }
            }
            __syncwarp();
        }

        __syncthreads();
        if (kt + 2 < nkt) issue(kt + 2, s);
    }

    // ---- epilogue: normalize, round, store (col-permuted for out proj) ----
    float inv0 = 1.f / l0, inv1 = 1.f / l1;
    float* a0p = at + (size_t)(b * SEQ + r0) * DIM + h * HD;
    float* a1p = at + (size_t)(b * SEQ + r0 + 8) * DIM + h * HD;
#pragma unroll
    for (int ni = 0; ni < 16; ni++) {
        a0p[ni * 8 + pp0] = f2tf32f(o[ni][0] * inv0);
        a0p[ni * 8 + pp1] = f2tf32f(o[ni][1] * inv0);
        a1p[ni * 8 + pp0] = f2tf32f(o[ni][2] * inv1);
        a1p[ni * 8 + pp1] = f2tf32f(o[ni][3] * inv1);
    }
}

// ---------------- RoPE table (fp32 angle, fp64 sincos) ----------------
__global__ void rope_table_kernel(float* cosT, float* sinT) {
    int s = blockIdx.x;
    int i = threadIdx.x;
    float inv = (float)pow(10000.0, -(double)(2 * i) / (double)HD);
    float ang = (float)s * inv;
    double a = (double)ang;
    cosT[s * HALF_HD + i] = (float)cos(a);
    sinT[s * HALF_HD + i] = (float)sin(a);
}

// ---------------- RoPE apply + transpose (+scale for Q) + round + d-perm ----------------
__global__ void rope_q_kernel(const float* __restrict__ qkvlin, const float* __restrict__ cosT,
                              const float* __restrict__ sinT, float* __restrict__ Q) {
    long idx = (long)blockIdx.x * blockDim.x + threadIdx.x;
    if (idx >= (long)BATCH * SEQ * NH * HALF_HD) return;
    int i = idx & (HALF_HD - 1);
    long t = idx >> 6;
    int h = t & (NH - 1); t >>= 4;
    int s = t & (SEQ - 1);
    int b = (int)(t >> 11);
    const float* src = qkvlin + ((long)(b * SEQ + s)) * (2 * DIM) + h * HD + 2 * i;
    float xr = src[0], xi = src[1];
    float c = cosT[s * HALF_HD + i], sn = sinT[s * HALF_HD + i];
    const float scale = 0.088388347648318447f;   // 1/sqrt(128)
    float* dst = Q + (((long)(b * NH + h) * SEQ + s)) * HD;
    int cr = 2 * i, ci = 2 * i + 1;
    dst[(cr & ~7) | PERM8(cr & 7)] = f2tf32f(scale * (xr * c - xi * sn));
    dst[(ci & ~7) | PERM8(ci & 7)] = f2tf32f(scale * (xr * sn + xi * c));
}

__global__ void rope_k_kernel(const float* __restrict__ qkvlin, const float* __restrict__ cosT,
                              const float* __restrict__ sinT, float* __restrict__ K) {
    long idx = (long)blockIdx.x * blockDim.x + threadIdx.x;
    if (idx >= (long)BATCH * SEQ * NKV * HALF_HD) return;
    int i = idx & (HALF_HD - 1);
    long t = idx >> 6;
    int h = t & (NKV - 1); t >>= 3;
    int s = t & (SEQ - 1);
    int b = (int)(t >> 11);
    const float* src = qkvlin + ((long)(b * SEQ + s)) * (2 * DIM) + DIM + h * HD + 2 * i;
    float xr = src[0], xi = src[1];
    float c = cosT[s * HALF_HD + i], sn = sinT[s * HALF_HD + i];
    float* dst = K + (((long)(b * NKV + h) * SEQ + s)) * HD;
    int cr = 2 * i, ci = 2 * i + 1;
    dst[(cr & ~7) | PERM8(cr & 7)] = f2tf32f(xr * c - xi * sn);
    dst[(ci & ~7) | PERM8(ci & 7)] = f2tf32f(xr * sn + xi * c);
}

// V transpose: qkvlin v-part [b,s,h,d] -> Vt[b,h,d,s'] (rounded, s 8-block permuted)
__global__ void v_transpose_kernel(const float* __restrict__ qkvlin, float* __restrict__ Vt) {
    __shared__ float t[32][33];
    int bh = blockIdx.z;
    int b = bh >> 3, h = bh & 7;
    int s0 = blockIdx.x * 32, d0 = blockIdx.y * 32;
    int tx = threadIdx.x, ty = threadIdx.y;
    for (int i = ty; i < 32; i += 8)
        t[i][tx] = qkvlin[((long)(b * SEQ + s0 + i)) * (2 * DIM) + (DIM + NKV * HD) + h * HD + d0 + tx];
    __syncthreads();
    int sp = (tx & ~7) | PERM8(tx & 7);
    for (int i = ty; i < 32; i += 8)
        Vt[((long)bh * HD + d0 + i) * SEQ + s0 + sp] = f2tf32f(t[tx][i]);
}

// ---------------- launch ----------------
extern "C" void kernel_launch(void* const* d_in, const int* in_sizes, int n_in,
                              void* d_out, int out_size) {
    const float* x  = (const float*)d_in[0];
    const float* wq = (const float*)d_in[1];
    const float* wk = (const float*)d_in[2];
    const float* wv = (const float*)d_in[3];
    const float* wo = (const float*)d_in[4];
    float* out = (float*)d_out;

    float* xr;   cudaGetSymbolAddress((void**)&xr,   g_xr);
    float* wqkv; cudaGetSymbolAddress((void**)&wqkv, g_wqkv);
    float* wor;  cudaGetSymbolAddress((void**)&wor,  g_wor);
    float* qkvl; cudaGetSymbolAddress((void**)&qkvl, g_qkvlin);
    float* Q;    cudaGetSymbolAddress((void**)&Q,    g_Q);
    float* Kd;   cudaGetSymbolAddress((void**)&Kd,   g_K);
    float* Vt;   cudaGetSymbolAddress((void**)&Vt,   g_Vt);
    float* at;   cudaGetSymbolAddress((void**)&at,   g_at);
    float* cT;   cudaGetSymbolAddress((void**)&cT,   g_cosT);
    float* sT;   cudaGetSymbolAddress((void**)&sT,   g_sinT);

    cudaFuncSetAttribute(flash_kernel, cudaFuncAttributeMaxDynamicSharedMemorySize, FLASH_SMEM);

    // 0) round+permute inputs; concat wq/wk/wv
    {
        long nx = (long)M_ROWS * DIM;
        round_perm_kernel<<<(unsigned)((nx + 255) / 256), 256>>>(x, xr, nx);
        long nw = (long)DIM * DIM;               // wq: 2048x2048
        long nk = (long)(NKV * HD) * DIM;        // wk/wv: 1024x2048
        round_perm_kernel<<<(unsigned)((nw + 255) / 256), 256>>>(wq, wqkv, nw);
        round_perm_kernel<<<(unsigned)((nk + 255) / 256), 256>>>(wk, wqkv + (long)DIM * DIM, nk);
        round_perm_kernel<<<(unsigned)((nk + 255) / 256), 256>>>(wv, wqkv + (long)(DIM + NKV * HD) * DIM, nk);
        round_perm_kernel<<<(unsigned)((nw + 255) / 256), 256>>>(wo, wor, nw);
    }

    // 1) RoPE table
    rope_table_kernel<<<SEQ, HALF_HD>>>(cT, sT);

    // 2) fused QKV projection: qkvlin[4096,4096] = xr @ wqkv^T
    mma_gemm<<<dim3(2 * DIM / 128, M_ROWS / 128), 256>>>(
        xr, DIM, wqkv, DIM, qkvl, 2 * DIM, DIM);

    // 3) RoPE + transposes (round + permute outputs)
    {
        long nq = (long)BATCH * SEQ * NH * HALF_HD;
        rope_q_kernel<<<(unsigned)((nq + 255) / 256), 256>>>(qkvl, cT, sT, Q);
        long nk = (long)BATCH * SEQ * NKV * HALF_HD;
        rope_k_kernel<<<(unsigned)((nk + 255) / 256), 256>>>(qkvl, cT, sT, Kd);
        v_transpose_kernel<<<dim3(SEQ / 32, HD / 32, BATCH * NKV), dim3(32, 8)>>>(qkvl, Vt);
    }

    // 4) fused causal attention -> at   (Bq=64 tiles)
    flash_kernel<<<dim3(SEQ / 64, BATCH * NH), 128, FLASH_SMEM>>>(Q, Kd, Vt, at);

    // 5) out = at @ wo^T
    mma_gemm<<<dim3(DIM / 128, M_ROWS / 128), 256>>>(
        at, DIM, wor, DIM, out, DIM, DIM);

    (void)in_sizes; (void)n_in; (void)out_size;
}

// round 9
// speedup vs baseline: 2.0720x; 1.9319x over previous
#include <cuda_runtime.h>
#include <cuda_bf16.h>
#include <cuda_fp16.h>
#include <cstdint>
#include <math.h>

// ---------------- problem constants ----------------
#define BATCH 2
#define SEQ   2048
#define DIM   2048
#define NH    16
#define NKV   8
#define HD    128
#define HALF_HD 64
#define M_ROWS (BATCH * SEQ)          // 4096
#define DIMP  (DIM / 2)               // 1024 packed (half2) cols
#define HDP   (HD / 2)                // 64 packed
#define SEQP  (SEQ / 2)               // 1024 packed keys

// 8-block permutation of the PACKED contraction dim: pos = (c&3)*2 | (c>>2)
// => positions (2q, 2q+1) hold packed cols (q, q+4) -> uint2 fragment loads
#define PERM8(c) ((((c) & 3) << 1) | ((c) >> 2))
#define PPOS(p) (((p) & ~7) | PERM8((p) & 7))

typedef unsigned int u32;

// ---------------- scratch (static device globals; no allocation) ----------------
__device__ u32   g_xr[(size_t)M_ROWS * DIMP];                  // x fp16-packed, K-permuted
__device__ u32   g_wqkv[(size_t)(2 * DIM) * DIMP];             // [wq;wk;wv] packed (4096 x 1024)
__device__ u32   g_wor[(size_t)DIM * DIMP];                    // wo packed
__device__ float g_qkvlin[(size_t)M_ROWS * 2 * DIM];           // x @ wqkv^T fp32 [4096, 4096]
__device__ u32   g_Q[(size_t)BATCH * NH  * SEQ * HDP];         // roped+scaled, d-packed+perm
__device__ u32   g_K[(size_t)BATCH * NKV * SEQ * HDP];         // roped, d-packed+perm
__device__ u32   g_Vt[(size_t)BATCH * NKV * HD * SEQP];        // [B,KV,D,Sp] keys packed+perm
__device__ u32   g_at[(size_t)M_ROWS * DIMP];                  // attn out packed+perm
__device__ float g_cosT[SEQ * HALF_HD];
__device__ float g_sinT[SEQ * HALF_HD];

// ---------------- PTX helpers ----------------
__device__ __forceinline__ u32 smem_u32(const void* p) {
    u32 a;
    asm("{ .reg .u64 t; cvta.to.shared.u64 t, %1; cvt.u32.u64 %0, t; }" : "=r"(a) : "l"(p));
    return a;
}
// pack two fp32 -> f16x2 (lo = first arg)
__device__ __forceinline__ u32 pack2(float lo, float hi) {
    u32 r;
    asm("cvt.rn.f16x2.f32 %0, %1, %2;" : "=r"(r) : "f"(hi), "f"(lo));
    return r;
}
__device__ __forceinline__ void cp_async16(u32 saddr, const void* g) {
    asm volatile("cp.async.cg.shared.global [%0], [%1], 16;" :: "r"(saddr), "l"(g));
}
#define CP_COMMIT() asm volatile("cp.async.commit_group;" ::: "memory")
#define CP_WAIT1()  asm volatile("cp.async.wait_group 1;" ::: "memory")

// m16n8k16 fp16 mma, fp32 accum. a0..a3 / b0,b1 are f16x2-packed u32.
__device__ __forceinline__ void mma16(float* c, u32 a0, u32 a1, u32 a2, u32 a3,
                                      u32 b0, u32 b1) {
    asm volatile("mma.sync.aligned.m16n8k16.row.col.f32.f16.f16.f32 "
        "{%0,%1,%2,%3}, {%4,%5,%6,%7}, {%8,%9}, {%0,%1,%2,%3};"
        : "+f"(c[0]), "+f"(c[1]), "+f"(c[2]), "+f"(c[3])
        : "r"(a0), "r"(a1), "r"(a2), "r"(a3), "r"(b0), "r"(b1));
}

// ---------------- round/pack + permute copy (fp32 pairs -> f16x2, packed-col perm) ----------------
__global__ void pack_perm_kernel(const float* __restrict__ in, u32* __restrict__ out, long np) {
    long i = (long)blockIdx.x * blockDim.x + threadIdx.x;   // packed index
    if (i < np) {
        float2 v = *(const float2*)(in + 2 * i);
        out[(i & ~7L) | PERM8((int)(i & 7))] = pack2(v.x, v.y);
    }
}

// ---------------- fp16 mma GEMM: C[M,N] = A[M,Kp] @ B[N,Kp]^T (packed operands) ----------------
#define AROW 24                       // 16 chunk + 8 pad (u32) -> conflict-free uint2 frags

__global__ __launch_bounds__(256) void mma_gemm(
    const u32* __restrict__ A, int lda,
    const u32* __restrict__ B, int ldb,
    float* __restrict__ C, int ldc, int Kp)
{
    int m0 = blockIdx.y * 128;
    int n0 = blockIdx.x * 128;
    int nch = Kp / 16;                // 16 packed (=32 orig K) per chunk

    __shared__ u32 sA[2][128][AROW];
    __shared__ u32 sB[2][128][AROW];

    int tid = threadIdx.x;
    int wid = tid >> 5;
    int lane = tid & 31;
    int wm0 = (wid & 1) * 64;
    int wn0 = (wid >> 1) * 32;
    int grp = lane >> 2;
    int qid = lane & 3;

    const u32* Ab = A + (long)m0 * lda;
    const u32* Bb = B + (long)n0 * ldb;

    auto issue = [&](int c, int s) {
        int k0 = c * 16;
#pragma unroll
        for (int i = 0; i < 2; i++) {
            int idx = tid + 256 * i;             // 0..511
            int row = idx >> 2;                  // 0..127
            int cc = idx & 3;                    // 16B chunk (4 u32)
            cp_async16(smem_u32(&sA[s][row][cc * 4]), Ab + (long)row * lda + k0 + cc * 4);
            cp_async16(smem_u32(&sB[s][row][cc * 4]), Bb + (long)row * ldb + k0 + cc * 4);
        }
        CP_COMMIT();
    };

    float acc[4][4][4] = {};

    issue(0, 0);
    issue(1, 1);

    for (int c = 0; c < nch; c++) {
        int s = c & 1;
        CP_WAIT1();
        __syncthreads();

#pragma unroll
        for (int ks = 0; ks < 16; ks += 8) {
            u32 a[4][4];
#pragma unroll
            for (int mi = 0; mi < 4; mi++) {
                int r = wm0 + mi * 16 + grp;
                uint2 x0 = *(const uint2*)&sA[s][r][ks + qid * 2];
                uint2 x1 = *(const uint2*)&sA[s][r + 8][ks + qid * 2];
                a[mi][0] = x0.x; a[mi][1] = x1.x; a[mi][2] = x0.y; a[mi][3] = x1.y;
            }
            u32 b[4][2];
#pragma unroll
            for (int ni = 0; ni < 4; ni++) {
                uint2 y = *(const uint2*)&sB[s][wn0 + ni * 8 + grp][ks + qid * 2];
                b[ni][0] = y.x; b[ni][1] = y.y;
            }
#pragma unroll
            for (int mi = 0; mi < 4; mi++)
#pragma unroll
                for (int ni = 0; ni < 4; ni++)
                    mma16(acc[mi][ni], a[mi][0], a[mi][1], a[mi][2], a[mi][3], b[ni][0], b[ni][1]);
        }
        __syncthreads();
        if (c + 2 < nch) issue(c + 2, s);
    }

#pragma unroll
    for (int mi = 0; mi < 4; mi++) {
#pragma unroll
        for (int ni = 0; ni < 4; ni++) {
            int row = m0 + wm0 + mi * 16 + grp;
            int col = n0 + wn0 + ni * 8 + 2 * qid;
            *(float2*)(C + (long)row * ldc + col) = make_float2(acc[mi][ni][0], acc[mi][ni][1]);
            *(float2*)(C + (long)(row + 8) * ldc + col) = make_float2(acc[mi][ni][2], acc[mi][ni][3]);
        }
    }
}

// ---------------- flash attention fp16: Bq=64, 4 warps, Q in regs, 2-stage cp.async ----------------
#define SKW 72                         // K stage row stride (64 packed + 8 pad) u32
#define SVW 24                         // V stage row stride (16 packed + 8 pad) u32
#define SKF (32 * SKW)                 // 2304 u32
#define SVF (128 * SVW)                // 3072 u32
#define SST (SKF + SVF)                // 5376 u32
#define SPW 20                         // P row stride (16 packed + 4 pad)
#define SPF (4 * 16 * SPW)             // 1280 u32

__global__ __launch_bounds__(128, 3) void flash_kernel(
    const u32* __restrict__ Q, const u32* __restrict__ K,
    const u32* __restrict__ Vt, u32* __restrict__ at)
{
    __shared__ u32 sm[2 * SST + SPF];  // 48128 B

    int tid = threadIdx.x, wid = tid >> 5, lane = tid & 31;
    int grp = lane >> 2, qid = lane & 3;
    u32* sP = sm + 2 * SST + wid * (16 * SPW);

    int bh = blockIdx.y;
    int b = bh >> 4, h = bh & 15, kv = h >> 1;
    int qt = (int)gridDim.x - 1 - (int)blockIdx.x;     // big tiles first
    int qbase = qt * 64;
    const u32* Qg = Q + (size_t)(b * NH + h) * SEQ * HDP;
    const u32* Kg = K + (size_t)(b * NKV + kv) * SEQ * HDP;
    const u32* Vg = Vt + (size_t)(b * NKV + kv) * HD * SEQP;

    int nkt = 2 * qt + 2;                              // 32-key tiles

    // stage fill: K 32 rows x 64 packed (16 cp16/row), V 128 rows x 16 packed (4 cp16/row)
    auto issue = [&](int kt, int s) {
        u32* sK = sm + s * SST;
        u32* sV = sK + SKF;
#pragma unroll
        for (int i = 0; i < 4; i++) {
            int idx = tid + 128 * i;                   // 0..511
            int krow = idx >> 4, kc4 = idx & 15;
            cp_async16(smem_u32(sK + krow * SKW + kc4 * 4),
                       Kg + (size_t)(kt * 32 + krow) * HDP + kc4 * 4);
            int vrow = idx >> 2, vc4 = idx & 3;
            cp_async16(smem_u32(sV + vrow * SVW + vc4 * 4),
                       Vg + (size_t)vrow * SEQP + kt * 16 + vc4 * 4);
        }
        CP_COMMIT();
    };

    issue(0, 0);
    issue(1, 1);

    // ---- this warp's Q rows (r0, r0+8) into registers ----
    int r0 = qbase + wid * 16 + grp;
    uint2 qa[8], qb[8];                                // per 8-packed block: (q, q+4)
#pragma unroll
    for (int kk = 0; kk < 8; kk++) {
        qa[kk] = *(const uint2*)(Qg + (size_t)r0 * HDP + kk * 8 + qid * 2);
        qb[kk] = *(const uint2*)(Qg + (size_t)(r0 + 8) * HDP + kk * 8 + qid * 2);
    }

    float o[16][4];
#pragma unroll
    for (int i = 0; i < 16; i++) { o[i][0] = o[i][1] = o[i][2] = o[i][3] = 0.f; }
    float m0 = -1e30f, m1 = -1e30f, l0 = 0.f, l1 = 0.f;

    for (int kt = 0; kt < nkt; kt++) {
        int s = kt & 1;
        u32* sK = sm + s * SST;
        u32* sV = sK + SKF;
        CP_WAIT1();
        __syncthreads();

        if (kt * 32 <= qbase + wid * 16 + 15) {        // warp has unmasked rows
            // ---- S = Q @ K^T (scale pre-folded into Q) ----
            float sc[4][4];
#pragma unroll
            for (int ni = 0; ni < 4; ni++) { sc[ni][0] = sc[ni][1] = sc[ni][2] = sc[ni][3] = 0.f; }
#pragma unroll
            for (int kk = 0; kk < 8; kk++) {
#pragma unroll
                for (int ni = 0; ni < 4; ni++) {
                    uint2 b01 = *(const uint2*)(sK + (ni * 8 + grp) * SKW + kk * 8 + qid * 2);
                    mma16(sc[ni], qa[kk].x, qb[kk].x, qa[kk].y, qb[kk].y, b01.x, b01.y);
                }
            }

            // ---- causal mask ----
            if (kt * 32 + 31 > qbase + wid * 16) {
#pragma unroll
                for (int ni = 0; ni < 4; ni++) {
                    int c0 = kt * 32 + ni * 8 + 2 * qid;
                    if (c0 > r0)         sc[ni][0] = -1e30f;
                    if (c0 + 1 > r0)     sc[ni][1] = -1e30f;
                    if (c0 > r0 + 8)     sc[ni][2] = -1e30f;
                    if (c0 + 1 > r0 + 8) sc[ni][3] = -1e30f;
                }
            }

            // ---- online softmax (rows r0, r0+8; quad-lane reductions) ----
            float mx0 = -1e30f, mx1 = -1e30f;
#pragma unroll
            for (int ni = 0; ni < 4; ni++) {
                mx0 = fmaxf(mx0, fmaxf(sc[ni][0], sc[ni][1]));
                mx1 = fmaxf(mx1, fmaxf(sc[ni][2], sc[ni][3]));
            }
            mx0 = fmaxf(mx0, __shfl_xor_sync(0xffffffffu, mx0, 1));
            mx0 = fmaxf(mx0, __shfl_xor_sync(0xffffffffu, mx0, 2));
            mx1 = fmaxf(mx1, __shfl_xor_sync(0xffffffffu, mx1, 1));
            mx1 = fmaxf(mx1, __shfl_xor_sync(0xffffffffu, mx1, 2));
            float mn0 = fmaxf(m0, mx0), mn1 = fmaxf(m1, mx1);
            float al0 = __expf(m0 - mn0), al1 = __expf(m1 - mn1);
            m0 = mn0; m1 = mn1;
            float sum0 = 0.f, sum1 = 0.f;
#pragma unroll
            for (int ni = 0; ni < 4; ni++) {
                sc[ni][0] = __expf(sc[ni][0] - mn0); sum0 += sc[ni][0];
                sc[ni][1] = __expf(sc[ni][1] - mn0); sum0 += sc[ni][1];
                sc[ni][2] = __expf(sc[ni][2] - mn1); sum1 += sc[ni][2];
                sc[ni][3] = __expf(sc[ni][3] - mn1); sum1 += sc[ni][3];
            }
            sum0 += __shfl_xor_sync(0xffffffffu, sum0, 1);
            sum0 += __shfl_xor_sync(0xffffffffu, sum0, 2);
            sum1 += __shfl_xor_sync(0xffffffffu, sum1, 1);
            sum1 += __shfl_xor_sync(0xffffffffu, sum1, 2);
            l0 = l0 * al0 + sum0;
            l1 = l1 * al1 + sum1;
#pragma unroll
            for (int ni = 0; ni < 16; ni++) {
                o[ni][0] *= al0; o[ni][1] *= al0;
                o[ni][2] *= al1; o[ni][3] *= al1;
            }

            // ---- stage P (fp16-packed key pairs, perm) into warp-private SMEM ----
#pragma unroll
            for (int ni = 0; ni < 4; ni++) {
                int pc = ni * 4 + qid;                 // packed key idx 0..15
                int pos = PPOS(pc);
                sP[grp * SPW + pos]       = pack2(sc[ni][0], sc[ni][1]);
                sP[(grp + 8) * SPW + pos] = pack2(sc[ni][2], sc[ni][3]);
            }
            __syncwarp();

            // ---- O += P @ V ----
            uint2 pa0[2], pa1[2];
#pragma unroll
            for (int kk = 0; kk < 2; kk++) {
                pa0[kk] = *(const uint2*)(sP + grp * SPW + kk * 8 + qid * 2);
                pa1[kk] = *(const uint2*)(sP + (grp + 8) * SPW + kk * 8 + qid * 2);
            }
#pragma unroll
            for (int ni = 0; ni < 16; ni++) {
#pragma unroll
                for (int kk = 0; kk < 2; kk++) {
                    uint2 b01 = *(const uint2*)(sV + (ni * 8 + grp) * SVW + kk * 8 + qid * 2);
                    mma16(o[ni], pa0[kk].x, pa1[kk].x, pa0[kk].y, pa1[kk].y, b01.x, b01.y);
                }
            }
            __syncwarp();
        }

        __syncthreads();
        if (kt + 2 < nkt) issue(kt + 2, s);
    }

    // ---- epilogue: normalize, pack fp16, store (packed-col perm for out proj) ----
    float inv0 = 1.f / l0, inv1 = 1.f / l1;
    u32* a0p = at + (size_t)(b * SEQ + r0) * DIMP + h * HDP;
    u32* a1p = at + (size_t)(b * SEQ + r0 + 8) * DIMP + h * HDP;
#pragma unroll
    for (int ni = 0; ni < 16; ni++) {
        int pc = ni * 4 + qid;                         // packed d idx 0..63
        int pos = PPOS(pc);
        a0p[pos] = pack2(o[ni][0] * inv0, o[ni][1] * inv0);
        a1p[pos] = pack2(o[ni][2] * inv1, o[ni][3] * inv1);
    }
}

// ---------------- RoPE table (fp32 angle, fp64 sincos) ----------------
__global__ void rope_table_kernel(float* cosT, float* sinT) {
    int s = blockIdx.x;
    int i = threadIdx.x;
    float inv = (float)pow(10000.0, -(double)(2 * i) / (double)HD);
    float ang = (float)s * inv;
    double a = (double)ang;
    cosT[s * HALF_HD + i] = (float)cos(a);
    sinT[s * HALF_HD + i] = (float)sin(a);
}

// ---------------- RoPE apply + transpose (+scale for Q) + pack fp16 + perm ----------------
__global__ void rope_q_kernel(const float* __restrict__ qkvlin, const float* __restrict__ cosT,
                              const float* __restrict__ sinT, u32* __restrict__ Q) {
    long idx = (long)blockIdx.x * blockDim.x + threadIdx.x;
    if (idx >= (long)BATCH * SEQ * NH * HALF_HD) return;
    int i = idx & (HALF_HD - 1);
    long t = idx >> 6;
    int h = t & (NH - 1); t >>= 4;
    int s = t & (SEQ - 1);
    int b = (int)(t >> 11);
    const float* src = qkvlin + ((long)(b * SEQ + s)) * (2 * DIM) + h * HD + 2 * i;
    float xr = src[0], xi = src[1];
    float c = cosT[s * HALF_HD + i], sn = sinT[s * HALF_HD + i];
    const float scale = 0.088388347648318447f;   // 1/sqrt(128)
    Q[(((long)(b * NH + h) * SEQ + s)) * HDP + PPOS(i)] =
        pack2(scale * (xr * c - xi * sn), scale * (xr * sn + xi * c));
}

__global__ void rope_k_kernel(const float* __restrict__ qkvlin, const float* __restrict__ cosT,
                              const float* __restrict__ sinT, u32* __restrict__ K) {
    long idx = (long)blockIdx.x * blockDim.x + threadIdx.x;
    if (idx >= (long)BATCH * SEQ * NKV * HALF_HD) return;
    int i = idx & (HALF_HD - 1);
    long t = idx >> 6;
    int h = t & (NKV - 1); t >>= 3;
    int s = t & (SEQ - 1);
    int b = (int)(t >> 11);
    const float* src = qkvlin + ((long)(b * SEQ + s)) * (2 * DIM) + DIM + h * HD + 2 * i;
    float xr = src[0], xi = src[1];
    float c = cosT[s * HALF_HD + i], sn = sinT[s * HALF_HD + i];
    K[(((long)(b * NKV + h) * SEQ + s)) * HDP + PPOS(i)] =
        pack2(xr * c - xi * sn, xr * sn + xi * c);
}

// V transpose: qkvlin v-part [b,s,h,d] -> Vt[b,h,d,ps] fp16 key pairs packed + perm
__global__ void v_transpose_kernel(const float* __restrict__ qkvlin, u32* __restrict__ Vt) {
    __shared__ float t[32][33];
    int bh = blockIdx.z;
    int b = bh >> 3, h = bh & 7;
    int s0 = blockIdx.x * 32, d0 = blockIdx.y * 32;
    int tx = threadIdx.x, ty = threadIdx.y;
    for (int i = ty; i < 32; i += 8)
        t[i][tx] = qkvlin[((long)(b * SEQ + s0 + i)) * (2 * DIM) + (DIM + NKV * HD) + h * HD + d0 + tx];
    __syncthreads();
    if (tx < 16) {
        int ps = s0 / 2 + tx;                          // global packed key idx
        long ppos = (long)((ps & ~7) | PERM8(ps & 7));
        for (int i = ty; i < 32; i += 8)
            Vt[((long)bh * HD + d0 + i) * SEQP + ppos] = pack2(t[2 * tx][i], t[2 * tx + 1][i]);
    }
}

// ---------------- launch ----------------
extern "C" void kernel_launch(void* const* d_in, const int* in_sizes, int n_in,
                              void* d_out, int out_size) {
    const float* x  = (const float*)d_in[0];
    const float* wq = (const float*)d_in[1];
    const float* wk = (const float*)d_in[2];
    const float* wv = (const float*)d_in[3];
    const float* wo = (const float*)d_in[4];
    float* out = (float*)d_out;

    u32* xr;     cudaGetSymbolAddress((void**)&xr,   g_xr);
    u32* wqkv;   cudaGetSymbolAddress((void**)&wqkv, g_wqkv);
    u32* wor;    cudaGetSymbolAddress((void**)&wor,  g_wor);
    float* qkvl; cudaGetSymbolAddress((void**)&qkvl, g_qkvlin);
    u32* Q;      cudaGetSymbolAddress((void**)&Q,    g_Q);
    u32* Kd;     cudaGetSymbolAddress((void**)&Kd,   g_K);
    u32* Vt;     cudaGetSymbolAddress((void**)&Vt,   g_Vt);
    u32* at;     cudaGetSymbolAddress((void**)&at,   g_at);
    float* cT;   cudaGetSymbolAddress((void**)&cT,   g_cosT);
    float* sT;   cudaGetSymbolAddress((void**)&sT,   g_sinT);

    // 0) pack+permute inputs to fp16; concat wq/wk/wv
    {
        long nx = (long)M_ROWS * DIMP;
        pack_perm_kernel<<<(unsigned)((nx + 255) / 256), 256>>>(x, xr, nx);
        long nw = (long)DIM * DIMP;              // wq: 2048 x 1024p
        long nk = (long)(NKV * HD) * DIMP;       // wk/wv: 1024 x 1024p
        pack_perm_kernel<<<(unsigned)((nw + 255) / 256), 256>>>(wq, wqkv, nw);
        pack_perm_kernel<<<(unsigned)((nk + 255) / 256), 256>>>(wk, wqkv + (long)DIM * DIMP, nk);
        pack_perm_kernel<<<(unsigned)((nk + 255) / 256), 256>>>(wv, wqkv + (long)(DIM + NKV * HD) * DIMP, nk);
        pack_perm_kernel<<<(unsigned)((nw + 255) / 256), 256>>>(wo, wor, nw);
    }

    // 1) RoPE table
    rope_table_kernel<<<SEQ, HALF_HD>>>(cT, sT);

    // 2) fused QKV projection: qkvlin[4096,4096] = xr @ wqkv^T  (Kp = 1024)
    mma_gemm<<<dim3(2 * DIM / 128, M_ROWS / 128), 256>>>(
        xr, DIMP, wqkv, DIMP, qkvl, 2 * DIM, DIMP);

    // 3) RoPE + transposes (pack fp16 + permute outputs)
    {
        long nq = (long)BATCH * SEQ * NH * HALF_HD;
        rope_q_kernel<<<(unsigned)((nq + 255) / 256), 256>>>(qkvl, cT, sT, Q);
        long nk = (long)BATCH * SEQ * NKV * HALF_HD;
        rope_k_kernel<<<(unsigned)((nk + 255) / 256), 256>>>(qkvl, cT, sT, Kd);
        v_transpose_kernel<<<dim3(SEQ / 32, HD / 32, BATCH * NKV), dim3(32, 8)>>>(qkvl, Vt);
    }

    // 4) fused causal attention -> at (fp16 packed)
    flash_kernel<<<dim3(SEQ / 64, BATCH * NH), 128>>>(Q, Kd, Vt, at);

    // 5) out = at @ wo^T  (Kp = 1024)
    mma_gemm<<<dim3(DIM / 128, M_ROWS / 128), 256>>>(
        at, DIMP, wor, DIMP, out, DIM, DIMP);

    (void)in_sizes; (void)n_in; (void)out_size;
}

// round 10
// speedup vs baseline: 2.2162x; 1.0696x over previous
#include <cuda_runtime.h>
#include <cuda_bf16.h>
#include <cuda_fp16.h>
#include <cstdint>
#include <math.h>

// ---------------- problem constants ----------------
#define BATCH 2
#define SEQ   2048
#define DIM   2048
#define NH    16
#define NKV   8
#define HD    128
#define HALF_HD 64
#define M_ROWS (BATCH * SEQ)          // 4096
#define DIMP  (DIM / 2)               // 1024 packed (half2) cols
#define HDP   (HD / 2)                // 64 packed
#define SEQP  (SEQ / 2)               // 1024 packed keys
#define KVD   (NKV * HD)              // 1024

// 8-block permutation of the PACKED contraction dim: pos = (c&3)*2 | (c>>2)
#define PERM8(c) ((((c) & 3) << 1) | ((c) >> 2))
#define PPOS(p) (((p) & ~7) | PERM8((p) & 7))

typedef unsigned int u32;

// ---------------- scratch (static device globals; no allocation) ----------------
__device__ u32   g_xr[(size_t)M_ROWS * DIMP];                  // x fp16-packed, K-permuted
__device__ u32   g_wqkv[(size_t)(2 * DIM) * DIMP];             // [wq;wk;wv] packed (4096 x 1024)
__device__ u32   g_wor[(size_t)DIM * DIMP];                    // wo packed
__device__ float g_vlin[(size_t)M_ROWS * KVD];                 // V projection fp32 [4096, 1024]
__device__ u32   g_Q[(size_t)BATCH * NH  * SEQ * HDP];         // roped+scaled, d-packed+perm
__device__ u32   g_K[(size_t)BATCH * NKV * SEQ * HDP];         // roped, d-packed+perm
__device__ u32   g_Vt[(size_t)BATCH * NKV * HD * SEQP];        // [B,KV,D,Sp] keys packed+perm
__device__ u32   g_at[(size_t)M_ROWS * DIMP];                  // attn out packed+perm
__device__ float g_cosT[SEQ * HALF_HD];
__device__ float g_sinT[SEQ * HALF_HD];

// ---------------- PTX helpers ----------------
__device__ __forceinline__ u32 smem_u32(const void* p) {
    u32 a;
    asm("{ .reg .u64 t; cvta.to.shared.u64 t, %1; cvt.u32.u64 %0, t; }" : "=r"(a) : "l"(p));
    return a;
}
__device__ __forceinline__ u32 pack2(float lo, float hi) {
    u32 r;
    asm("cvt.rn.f16x2.f32 %0, %1, %2;" : "=r"(r) : "f"(hi), "f"(lo));
    return r;
}
__device__ __forceinline__ void cp_async16(u32 saddr, const void* g) {
    asm volatile("cp.async.cg.shared.global [%0], [%1], 16;" :: "r"(saddr), "l"(g));
}
#define CP_COMMIT() asm volatile("cp.async.commit_group;" ::: "memory")
#define CP_WAIT1()  asm volatile("cp.async.wait_group 1;" ::: "memory")

__device__ __forceinline__ void mma16(float* c, u32 a0, u32 a1, u32 a2, u32 a3,
                                      u32 b0, u32 b1) {
    asm volatile("mma.sync.aligned.m16n8k16.row.col.f32.f16.f16.f32 "
        "{%0,%1,%2,%3}, {%4,%5,%6,%7}, {%8,%9}, {%0,%1,%2,%3};"
        : "+f"(c[0]), "+f"(c[1]), "+f"(c[2]), "+f"(c[3])
        : "r"(a0), "r"(a1), "r"(a2), "r"(a3), "r"(b0), "r"(b1));
}

// ---------------- pack + permute copy (fp32 pairs -> f16x2, packed-col perm) ----------------
__global__ void pack_perm_kernel(const float* __restrict__ in, u32* __restrict__ out, long np) {
    long i = (long)blockIdx.x * blockDim.x + threadIdx.x;
    if (i < np) {
        float2 v = *(const float2*)(in + 2 * i);
        out[(i & ~7L) | PERM8((int)(i & 7))] = pack2(v.x, v.y);
    }
}

// ---------------- fp16 mma GEMM: C[M,N] = A[M,Kp] @ B[N,Kp]^T ----------------
// MODE 0: plain fp32 C store. MODE 1: fused QKV epilogue (RoPE+scale+pack for Q/K cols,
// fp32 V slice to Vo).
#define AROW 24

template <int MODE>
__global__ __launch_bounds__(256) void mma_gemm(
    const u32* __restrict__ A, int lda,
    const u32* __restrict__ B, int ldb,
    float* __restrict__ C, int ldc, int Kp,
    const float* __restrict__ cosT, const float* __restrict__ sinT,
    u32* __restrict__ Qo, u32* __restrict__ Ko, float* __restrict__ Vo)
{
    int m0 = blockIdx.y * 128;
    int n0 = blockIdx.x * 128;
    int nch = Kp / 16;

    __shared__ u32 sA[2][128][AROW];
    __shared__ u32 sB[2][128][AROW];

    int tid = threadIdx.x;
    int wid = tid >> 5;
    int lane = tid & 31;
    int wm0 = (wid & 1) * 64;
    int wn0 = (wid >> 1) * 32;
    int grp = lane >> 2;
    int qid = lane & 3;

    const u32* Ab = A + (long)m0 * lda;
    const u32* Bb = B + (long)n0 * ldb;

    auto issue = [&](int c, int s) {
        int k0 = c * 16;
#pragma unroll
        for (int i = 0; i < 2; i++) {
            int idx = tid + 256 * i;
            int row = idx >> 2;
            int cc = idx & 3;
            cp_async16(smem_u32(&sA[s][row][cc * 4]), Ab + (long)row * lda + k0 + cc * 4);
            cp_async16(smem_u32(&sB[s][row][cc * 4]), Bb + (long)row * ldb + k0 + cc * 4);
        }
        CP_COMMIT();
    };

    float acc[4][4][4] = {};

    issue(0, 0);
    issue(1, 1);

    for (int c = 0; c < nch; c++) {
        int s = c & 1;
        CP_WAIT1();
        __syncthreads();

#pragma unroll
        for (int ks = 0; ks < 16; ks += 8) {
            u32 a[4][4];
#pragma unroll
            for (int mi = 0; mi < 4; mi++) {
                int r = wm0 + mi * 16 + grp;
                uint2 x0 = *(const uint2*)&sA[s][r][ks + qid * 2];
                uint2 x1 = *(const uint2*)&sA[s][r + 8][ks + qid * 2];
                a[mi][0] = x0.x; a[mi][1] = x1.x; a[mi][2] = x0.y; a[mi][3] = x1.y;
            }
            u32 b[4][2];
#pragma unroll
            for (int ni = 0; ni < 4; ni++) {
                uint2 y = *(const uint2*)&sB[s][wn0 + ni * 8 + grp][ks + qid * 2];
                b[ni][0] = y.x; b[ni][1] = y.y;
            }
#pragma unroll
            for (int mi = 0; mi < 4; mi++)
#pragma unroll
                for (int ni = 0; ni < 4; ni++)
                    mma16(acc[mi][ni], a[mi][0], a[mi][1], a[mi][2], a[mi][3], b[ni][0], b[ni][1]);
        }
        __syncthreads();
        if (c + 2 < nch) issue(c + 2, s);
    }

#pragma unroll
    for (int mi = 0; mi < 4; mi++) {
#pragma unroll
        for (int ni = 0; ni < 4; ni++) {
            int row = m0 + wm0 + mi * 16 + grp;
            int col = n0 + wn0 + ni * 8 + 2 * qid;
            float v00 = acc[mi][ni][0], v01 = acc[mi][ni][1];
            float v10 = acc[mi][ni][2], v11 = acc[mi][ni][3];
            if (MODE == 0) {
                *(float2*)(C + (long)row * ldc + col) = make_float2(v00, v01);
                *(float2*)(C + (long)(row + 8) * ldc + col) = make_float2(v10, v11);
            } else {
                int b = row >> 11, s = row & (SEQ - 1);
                if (col < DIM) {                       // Q region: rope + scale + pack
                    int h = col >> 7, i = (col & 127) >> 1;
                    float c0 = cosT[s * HALF_HD + i],       s0 = sinT[s * HALF_HD + i];
                    float c1 = cosT[(s + 8) * HALF_HD + i], s1 = sinT[(s + 8) * HALF_HD + i];
                    const float sc = 0.088388347648318447f;
                    size_t base = (size_t)(b * NH + h) * SEQ;
                    Qo[(base + s) * HDP + PPOS(i)] =
                        pack2(sc * (v00 * c0 - v01 * s0), sc * (v00 * s0 + v01 * c0));
                    Qo[(base + s + 8) * HDP + PPOS(i)] =
                        pack2(sc * (v10 * c1 - v11 * s1), sc * (v10 * s1 + v11 * c1));
                } else if (col < DIM + KVD) {          // K region: rope + pack
                    int c2 = col - DIM;
                    int h = c2 >> 7, i = (c2 & 127) >> 1;
                    float c0 = cosT[s * HALF_HD + i],       s0 = sinT[s * HALF_HD + i];
                    float c1 = cosT[(s + 8) * HALF_HD + i], s1 = sinT[(s + 8) * HALF_HD + i];
                    size_t base = (size_t)(b * NKV + h) * SEQ;
                    Ko[(base + s) * HDP + PPOS(i)] =
                        pack2(v00 * c0 - v01 * s0, v00 * s0 + v01 * c0);
                    Ko[(base + s + 8) * HDP + PPOS(i)] =
                        pack2(v10 * c1 - v11 * s1, v10 * s1 + v11 * c1);
                } else {                               // V region: fp32 to Vo
                    int c2 = col - (DIM + KVD);
                    *(float2*)(Vo + (size_t)row * KVD + c2) = make_float2(v00, v01);
                    *(float2*)(Vo + (size_t)(row + 8) * KVD + c2) = make_float2(v10, v11);
                }
            }
        }
    }
}

// ---------------- flash attention fp16: Bq=64, Bk=64, 4 warps, Q in regs ----------------
#define SKW 72                         // K row stride (64 packed + 8 pad) u32
#define SVW 40                         // V row stride (32 packed + 8 pad) u32
#define SKF (64 * SKW)                 // 4608 u32
#define SVF (128 * SVW)                // 5120 u32
#define SST (SKF + SVF)                // 9728 u32
#define SPW 36                         // P row stride (32 packed + 4 pad)
#define SPF (4 * 16 * SPW)             // 2304 u32
#define FLASH_SMEM ((2 * SST + SPF) * 4)   // 87040 B -> 2 CTAs/SM

__global__ __launch_bounds__(128) void flash_kernel(
    const u32* __restrict__ Q, const u32* __restrict__ K,
    const u32* __restrict__ Vt, u32* __restrict__ at)
{
    extern __shared__ u32 sm[];

    int tid = threadIdx.x, wid = tid >> 5, lane = tid & 31;
    int grp = lane >> 2, qid = lane & 3;
    u32* sP = sm + 2 * SST + wid * (16 * SPW);

    int bh = blockIdx.y;
    int b = bh >> 4, h = bh & 15, kv = h >> 1;
    int qt = (int)gridDim.x - 1 - (int)blockIdx.x;     // big tiles first
    int qbase = qt * 64;
    const u32* Qg = Q + (size_t)(b * NH + h) * SEQ * HDP;
    const u32* Kg = K + (size_t)(b * NKV + kv) * SEQ * HDP;
    const u32* Vg = Vt + (size_t)(b * NKV + kv) * HD * SEQP;

    int nkt = qt + 1;                                  // 64-key tiles

    // stage fill: K 64 rows x 64 packed (16 cp16/row), V 128 rows x 32 packed (8 cp16/row)
    auto issue = [&](int kt, int s) {
        u32* sK = sm + s * SST;
        u32* sV = sK + SKF;
#pragma unroll
        for (int i = 0; i < 8; i++) {
            int idx = tid + 128 * i;                   // 0..1023
            int krow = idx >> 4, kc4 = idx & 15;
            cp_async16(smem_u32(sK + krow * SKW + kc4 * 4),
                       Kg + (size_t)(kt * 64 + krow) * HDP + kc4 * 4);
            int vrow = idx >> 3, vc4 = idx & 7;
            cp_async16(smem_u32(sV + vrow * SVW + vc4 * 4),
                       Vg + (size_t)vrow * SEQP + kt * 32 + vc4 * 4);
        }
        CP_COMMIT();
    };

    issue(0, 0);
    if (nkt > 1) issue(1, 1); else CP_COMMIT();        // keep wait_group count consistent

    // ---- this warp's Q rows (r0, r0+8) into registers ----
    int r0 = qbase + wid * 16 + grp;
    uint2 qa[8], qb[8];
#pragma unroll
    for (int kk = 0; kk < 8; kk++) {
        qa[kk] = *(const uint2*)(Qg + (size_t)r0 * HDP + kk * 8 + qid * 2);
        qb[kk] = *(const uint2*)(Qg + (size_t)(r0 + 8) * HDP + kk * 8 + qid * 2);
    }

    float o[16][4];
#pragma unroll
    for (int i = 0; i < 16; i++) { o[i][0] = o[i][1] = o[i][2] = o[i][3] = 0.f; }
    float m0 = -1e30f, m1 = -1e30f, l0 = 0.f, l1 = 0.f;

    for (int kt = 0; kt < nkt; kt++) {
        int s = kt & 1;
        u32* sK = sm + s * SST;
        u32* sV = sK + SKF;
        CP_WAIT1();
        __syncthreads();

        // ---- S = Q @ K^T (64 keys; scale pre-folded into Q) ----
        float scv[8][4];
#pragma unroll
        for (int ni = 0; ni < 8; ni++) { scv[ni][0] = scv[ni][1] = scv[ni][2] = scv[ni][3] = 0.f; }
#pragma unroll
        for (int kk = 0; kk < 8; kk++) {
#pragma unroll
            for (int ni = 0; ni < 8; ni++) {
                uint2 b01 = *(const uint2*)(sK + (ni * 8 + grp) * SKW + kk * 8 + qid * 2);
                mma16(scv[ni], qa[kk].x, qb[kk].x, qa[kk].y, qb[kk].y, b01.x, b01.y);
            }
        }

        // ---- causal mask (only the diagonal tile kt == qt) ----
        if (kt == qt) {
#pragma unroll
            for (int ni = 0; ni < 8; ni++) {
                int c0 = kt * 64 + ni * 8 + 2 * qid;
                if (c0 > r0)         scv[ni][0] = -1e30f;
                if (c0 + 1 > r0)     scv[ni][1] = -1e30f;
                if (c0 > r0 + 8)     scv[ni][2] = -1e30f;
                if (c0 + 1 > r0 + 8) scv[ni][3] = -1e30f;
            }
        }

        // ---- online softmax (rows r0, r0+8; quad-lane reductions) ----
        float mx0 = -1e30f, mx1 = -1e30f;
#pragma unroll
        for (int ni = 0; ni < 8; ni++) {
            mx0 = fmaxf(mx0, fmaxf(scv[ni][0], scv[ni][1]));
            mx1 = fmaxf(mx1, fmaxf(scv[ni][2], scv[ni][3]));
        }
        mx0 = fmaxf(mx0, __shfl_xor_sync(0xffffffffu, mx0, 1));
        mx0 = fmaxf(mx0, __shfl_xor_sync(0xffffffffu, mx0, 2));
        mx1 = fmaxf(mx1, __shfl_xor_sync(0xffffffffu, mx1, 1));
        mx1 = fmaxf(mx1, __shfl_xor_sync(0xffffffffu, mx1, 2));
        float mn0 = fmaxf(m0, mx0), mn1 = fmaxf(m1, mx1);
        float al0 = __expf(m0 - mn0), al1 = __expf(m1 - mn1);
        m0 = mn0; m1 = mn1;
        float sum0 = 0.f, sum1 = 0.f;
#pragma unroll
        for (int ni = 0; ni < 8; ni++) {
            scv[ni][0] = __expf(scv[ni][0] - mn0); sum0 += scv[ni][0];
            scv[ni][1] = __expf(scv[ni][1] - mn0); sum0 += scv[ni][1];
            scv[ni][2] = __expf(scv[ni][2] - mn1); sum1 += scv[ni][2];
            scv[ni][3] = __expf(scv[ni][3] - mn1); sum1 += scv[ni][3];
        }
        sum0 += __shfl_xor_sync(0xffffffffu, sum0, 1);
        sum0 += __shfl_xor_sync(0xffffffffu, sum0, 2);
        sum1 += __shfl_xor_sync(0xffffffffu, sum1, 1);
        sum1 += __shfl_xor_sync(0xffffffffu, sum1, 2);
        l0 = l0 * al0 + sum0;
        l1 = l1 * al1 + sum1;
#pragma unroll
        for (int ni = 0; ni < 16; ni++) {
            o[ni][0] *= al0; o[ni][1] *= al0;
            o[ni][2] *= al1; o[ni][3] *= al1;
        }

        // ---- stage P (fp16-packed key pairs, perm) into warp-private SMEM ----
#pragma unroll
        for (int ni = 0; ni < 8; ni++) {
            int pc = ni * 4 + qid;                     // packed key idx 0..31
            int pos = PPOS(pc);
            sP[grp * SPW + pos]       = pack2(scv[ni][0], scv[ni][1]);
            sP[(grp + 8) * SPW + pos] = pack2(scv[ni][2], scv[ni][3]);
        }
        __syncwarp();

        // ---- O += P @ V ----
        uint2 pa0[4], pa1[4];
#pragma unroll
        for (int kk = 0; kk < 4; kk++) {
            pa0[kk] = *(const uint2*)(sP + grp * SPW + kk * 8 + qid * 2);
            pa1[kk] = *(const uint2*)(sP + (grp + 8) * SPW + kk * 8 + qid * 2);
        }
#pragma unroll
        for (int ni = 0; ni < 16; ni++) {
#pragma unroll
            for (int kk = 0; kk < 4; kk++) {
                uint2 b01 = *(const uint2*)(sV + (ni * 8 + grp) * SVW + kk * 8 + qid * 2);
                mma16(o[ni], pa0[kk].x, pa1[kk].x, pa0[kk].y, pa1[kk].y, b01.x, b01.y);
            }
        }
        __syncwarp();

        __syncthreads();
        if (kt + 2 < nkt) issue(kt + 2, s);
    }

    // ---- epilogue: normalize, pack fp16, store (packed-col perm for out proj) ----
    float inv0 = 1.f / l0, inv1 = 1.f / l1;
    u32* a0p = at + (size_t)(b * SEQ + r0) * DIMP + h * HDP;
    u32* a1p = at + (size_t)(b * SEQ + r0 + 8) * DIMP + h * HDP;
#pragma unroll
    for (int ni = 0; ni < 16; ni++) {
        int pc = ni * 4 + qid;
        int pos = PPOS(pc);
        a0p[pos] = pack2(o[ni][0] * inv0, o[ni][1] * inv0);
        a1p[pos] = pack2(o[ni][2] * inv1, o[ni][3] * inv1);
    }
}

// ---------------- RoPE table (fp32 angle, fp64 sincos) ----------------
__global__ void rope_table_kernel(float* cosT, float* sinT) {
    int s = blockIdx.x;
    int i = threadIdx.x;
    float inv = (float)pow(10000.0, -(double)(2 * i) / (double)HD);
    float ang = (float)s * inv;
    double a = (double)ang;
    cosT[s * HALF_HD + i] = (float)cos(a);
    sinT[s * HALF_HD + i] = (float)sin(a);
}

// V transpose: vlin [b*SEQ+s, h*HD+d] -> Vt[b,h,d,ps] fp16 key pairs packed + perm
__global__ void v_transpose_kernel(const float* __restrict__ vlin, u32* __restrict__ Vt) {
    __shared__ float t[32][33];
    int bh = blockIdx.z;
    int b = bh >> 3, h = bh & 7;
    int s0 = blockIdx.x * 32, d0 = blockIdx.y * 32;
    int tx = threadIdx.x, ty = threadIdx.y;
    for (int i = ty; i < 32; i += 8)
        t[i][tx] = vlin[((long)(b * SEQ + s0 + i)) * KVD + h * HD + d0 + tx];
    __syncthreads();
    if (tx < 16) {
        int ps = s0 / 2 + tx;
        long ppos = (long)((ps & ~7) | PERM8(ps & 7));
        for (int i = ty; i < 32; i += 8)
            Vt[((long)bh * HD + d0 + i) * SEQP + ppos] = pack2(t[2 * tx][i], t[2 * tx + 1][i]);
    }
}

// ---------------- launch ----------------
extern "C" void kernel_launch(void* const* d_in, const int* in_sizes, int n_in,
                              void* d_out, int out_size) {
    const float* x  = (const float*)d_in[0];
    const float* wq = (const float*)d_in[1];
    const float* wk = (const float*)d_in[2];
    const float* wv = (const float*)d_in[3];
    const float* wo = (const float*)d_in[4];
    float* out = (float*)d_out;

    u32* xr;     cudaGetSymbolAddress((void**)&xr,   g_xr);
    u32* wqkv;   cudaGetSymbolAddress((void**)&wqkv, g_wqkv);
    u32* wor;    cudaGetSymbolAddress((void**)&wor,  g_wor);
    float* vlin; cudaGetSymbolAddress((void**)&vlin, g_vlin);
    u32* Q;      cudaGetSymbolAddress((void**)&Q,    g_Q);
    u32* Kd;     cudaGetSymbolAddress((void**)&Kd,   g_K);
    u32* Vt;     cudaGetSymbolAddress((void**)&Vt,   g_Vt);
    u32* at;     cudaGetSymbolAddress((void**)&at,   g_at);
    float* cT;   cudaGetSymbolAddress((void**)&cT,   g_cosT);
    float* sT;   cudaGetSymbolAddress((void**)&sT,   g_sinT);

    cudaFuncSetAttribute(flash_kernel, cudaFuncAttributeMaxDynamicSharedMemorySize, FLASH_SMEM);

    // 0) pack+permute inputs to fp16; concat wq/wk/wv
    {
        long nx = (long)M_ROWS * DIMP;
        pack_perm_kernel<<<(unsigned)((nx + 255) / 256), 256>>>(x, xr, nx);
        long nw = (long)DIM * DIMP;
        long nk = (long)KVD * DIMP;
        pack_perm_kernel<<<(unsigned)((nw + 255) / 256), 256>>>(wq, wqkv, nw);
        pack_perm_kernel<<<(unsigned)((nk + 255) / 256), 256>>>(wk, wqkv + (long)DIM * DIMP, nk);
        pack_perm_kernel<<<(unsigned)((nk + 255) / 256), 256>>>(wv, wqkv + (long)(DIM + KVD) * DIMP, nk);
        pack_perm_kernel<<<(unsigned)((nw + 255) / 256), 256>>>(wo, wor, nw);
    }

    // 1) RoPE table (must precede fused QKV GEMM)
    rope_table_kernel<<<SEQ, HALF_HD>>>(cT, sT);

    // 2) fused QKV projection with RoPE/pack epilogue -> g_Q, g_K, g_vlin
    mma_gemm<1><<<dim3(2 * DIM / 128, M_ROWS / 128), 256>>>(
        xr, DIMP, wqkv, DIMP, nullptr, 0, DIMP, cT, sT, Q, Kd, vlin);

    // 3) V transpose (fp32 vlin -> packed Vt)
    v_transpose_kernel<<<dim3(SEQ / 32, HD / 32, BATCH * NKV), dim3(32, 8)>>>(vlin, Vt);

    // 4) fused causal attention -> at (fp16 packed), Bq=64/Bk=64
    flash_kernel<<<dim3(SEQ / 64, BATCH * NH), 128, FLASH_SMEM>>>(Q, Kd, Vt, at);

    // 5) out = at @ wo^T
    mma_gemm<0><<<dim3(DIM / 128, M_ROWS / 128), 256>>>(
        at, DIMP, wor, DIMP, out, DIM, DIMP, nullptr, nullptr, nullptr, nullptr, nullptr);

    (void)in_sizes; (void)n_in; (void)out_size;
}